// round 13
// baseline (speedup 1.0000x reference)
#include <cuda_runtime.h>
#include <cuda_bf16.h>
#include <cstdint>

#define B_    512
#define T_    2048
#define D_    64
#define H_    66
#define G4    264
#define BG    (B_ * G4)          // x_proj stride per t: [T][B][G4]
#define MT    128                // t-rows per proj block
#define PADW  72                 // proj smem row pad (bf16)
// lstm_mma config
#define LB    16                 // batches per lstm block
#define LNB   (B_ / LB)          // 32 blocks
#define LTHR  352                // 11 warps: 3 n8-tiles each (33 total)
#define KP    88                 // padded K row (bf16) -> 176B stride, LDSM conflict-free

__device__ float    g_xproj[(size_t)T_ * B_ * G4];   // raw GEMM (no bias)
__device__ float    g_hT[B_ * H_];
__device__ unsigned g_done = 0;

__device__ __forceinline__ float sigm_(float x) {
    return __fdividef(1.f, 1.f + __expf(-x));
}

// ================= mma.sync helpers =================
__device__ __forceinline__ uint32_t smem_u32(const void* p) {
    uint32_t a;
    asm("{ .reg .u64 t; cvta.to.shared.u64 t, %1; cvt.u32.u64 %0, t; }" : "=r"(a) : "l"(p));
    return a;
}
#define LDSM_X4(r, a) \
    asm volatile("ldmatrix.sync.aligned.m8n8.x4.shared.b16 {%0,%1,%2,%3}, [%4];" \
        : "=r"((r)[0]),"=r"((r)[1]),"=r"((r)[2]),"=r"((r)[3]) : "r"(a))
#define LDSM_X2(r, a) \
    asm volatile("ldmatrix.sync.aligned.m8n8.x2.shared.b16 {%0,%1}, [%2];" \
        : "=r"((r)[0]),"=r"((r)[1]) : "r"(a))
#define MMA_BF16(d, a, bb) \
    asm volatile("mma.sync.aligned.m16n8k16.row.col.f32.bf16.bf16.f32 " \
        "{%0,%1,%2,%3}, {%4,%5,%6,%7}, {%8,%9}, {%0,%1,%2,%3};" \
        : "+f"((d)[0]),"+f"((d)[1]),"+f"((d)[2]),"+f"((d)[3]) \
        : "r"((a)[0]),"r"((a)[1]),"r"((a)[2]),"r"((a)[3]), "r"((bb)[0]),"r"((bb)[1]))

__device__ __forceinline__ uint32_t pack_bf16(__nv_bfloat16 lo, __nv_bfloat16 hi) {
    return ((uint32_t)__bfloat16_as_ushort(hi) << 16) | (uint32_t)__bfloat16_as_ushort(lo);
}
__device__ __forceinline__ void split_f4(float4 v, uint2& h, uint2& l) {
    const __nv_bfloat16 h0 = __float2bfloat16(v.x), h1 = __float2bfloat16(v.y),
                        h2 = __float2bfloat16(v.z), h3 = __float2bfloat16(v.w);
    h.x = pack_bf16(h0, h1); h.y = pack_bf16(h2, h3);
    l.x = pack_bf16(__float2bfloat16(v.x - __bfloat162float(h0)),
                    __float2bfloat16(v.y - __bfloat162float(h1)));
    l.y = pack_bf16(__float2bfloat16(v.z - __bfloat162float(h2)),
                    __float2bfloat16(v.w - __bfloat162float(h3)));
}

// ================= projection (R11, validated) =================
#define XS_HI 0
#define XS_LO (XS_HI + MT * PADW * 2)
#define WS_HI (XS_LO + MT * PADW * 2)
#define WS_LO (WS_HI + G4 * PADW * 2)
#define PSM_TOT (WS_LO + G4 * PADW * 2)

__global__ __launch_bounds__(256, 1) void proj_mma(const float* __restrict__ x,
                                                   const float* __restrict__ W_ih)
{
    extern __shared__ __align__(16) char smem[];
    const uint32_t sb = smem_u32(smem);
    const int tid  = threadIdx.x;
    const int w    = tid >> 5, lane = tid & 31;
    const int b    = blockIdx.x >> 4;
    const int t0   = (blockIdx.x & 15) * MT;

    {
        const float4* wg = (const float4*)W_ih;
        for (int i = tid; i < G4 * (D_ / 4); i += 256) {
            const int row = i >> 4, c4 = (i & 15) * 4;
            uint2 h, l; split_f4(wg[i], h, l);
            const uint32_t off = (uint32_t)(row * PADW + c4) * 2;
            *(uint2*)(smem + WS_HI + off) = h;
            *(uint2*)(smem + WS_LO + off) = l;
        }
    }
    {
        const float4* xg = (const float4*)(x + ((size_t)b * T_ + t0) * D_);
        for (int i = tid; i < MT * (D_ / 4); i += 256) {
            const int row = i >> 4, c4 = (i & 15) * 4;
            uint2 h, l; split_f4(xg[i], h, l);
            const uint32_t off = (uint32_t)(row * PADW + c4) * 2;
            *(uint2*)(smem + XS_HI + off) = h;
            *(uint2*)(smem + XS_LO + off) = l;
        }
    }
    __syncthreads();

    uint32_t aHi[4][4], aLo[4][4];
    {
        const int mat = lane >> 3, r = lane & 7;
        const int row = 16 * w + ((mat & 1) << 3) + r;
        const int colb = (mat >> 1) << 3;
        #pragma unroll
        for (int kc = 0; kc < 4; kc++) {
            const uint32_t o = (uint32_t)(row * PADW + kc * 16 + colb) * 2;
            LDSM_X4(aHi[kc], sb + XS_HI + o);
            LDSM_X4(aLo[kc], sb + XS_LO + o);
        }
    }

    const int L = lane & 15;
    const int nr   = L & 7;
    const int colb = (L >> 3) << 3;
    const int mrow = lane >> 2;
    const int ccol = (lane & 3) * 2;

    for (int nt = 0; nt < 33; nt++) {
        uint32_t bHi[4][2], bLo[4][2];
        const int n = nt * 8 + nr;
        #pragma unroll
        for (int kc = 0; kc < 4; kc++) {
            const uint32_t o = (uint32_t)(n * PADW + kc * 16 + colb) * 2;
            LDSM_X2(bHi[kc], sb + WS_HI + o);
            LDSM_X2(bLo[kc], sb + WS_LO + o);
        }
        float c[4] = {0.f, 0.f, 0.f, 0.f};
        #pragma unroll
        for (int kc = 0; kc < 4; kc++) {
            MMA_BF16(c, aHi[kc], bHi[kc]);
            MMA_BF16(c, aHi[kc], bLo[kc]);
            MMA_BF16(c, aLo[kc], bHi[kc]);
        }
        float* op = g_xproj + (size_t)(t0 + 16 * w + mrow) * BG
                  + (size_t)b * G4 + nt * 8 + ccol;
        *(float2*)op                      = make_float2(c[0], c[1]);
        *(float2*)(op + (size_t)8 * BG)   = make_float2(c[2], c[3]);
    }
}

// ================= recurrence on HMMA =================
// smem (dynamic): A (h bf16 hi/lo) then a region used first for W split,
// then reused for xp double-buffer + gates.
#define A_HI_  0
#define A_LO_  (LB * 176)                 // 2816
#define UNI_   (2 * LB * 176)             // 5632
#define W_HI_  (UNI_)
#define W_LO_  (UNI_ + G4 * 176)          // + 46464
#define XP_    (UNI_)                     // 2 * 16*264*4 = 33792
#define GT_    (UNI_ + 2 * LB * G4 * 4)   // + 33792
#define LSM_TOT (UNI_ + 2 * G4 * 176)     // 98560

__global__ __launch_bounds__(LTHR, 1) void lstm_mma(
    const float* __restrict__ W_hh,  const float* __restrict__ b_ih,
    const float* __restrict__ b_hh,  const float* __restrict__ gamma,
    const float* __restrict__ beta,  const float* __restrict__ fc_w,
    const float* __restrict__ fc_b,  float* __restrict__ out)
{
    extern __shared__ __align__(16) char sm[];
    const uint32_t sb = smem_u32(sm);
    const int tid = threadIdx.x, w = tid >> 5, lane = tid & 31;
    const int b0  = blockIdx.x * LB;
    __shared__ unsigned s_last;
    __shared__ float s_a[H_], s_b[H_];

    // ---- zero A (h = 0, incl. k-pad) ----
    for (int i = tid; i < UNI_ / 4; i += LTHR) ((uint32_t*)sm)[i] = 0;

    // ---- split W_hh -> W smem (bf16 hi/lo, k-padded) ----
    for (int i = tid; i < G4 * KP; i += LTHR) {
        const int row = i / KP, col = i % KP;
        const float v = (col < H_) ? W_hh[row * H_ + col] : 0.f;
        const __nv_bfloat16 hi = __float2bfloat16(v);
        const __nv_bfloat16 lo = __float2bfloat16(v - __bfloat162float(hi));
        *(unsigned short*)(sm + W_HI_ + row * 176 + col * 2) = __bfloat16_as_ushort(hi);
        *(unsigned short*)(sm + W_LO_ + row * 176 + col * 2) = __bfloat16_as_ushort(lo);
    }
    __syncthreads();

    // ---- persistent B fragments: 3 n8-tiles per warp ----
    uint32_t bHi[3][5][2], bLo[3][5][2];
    {
        const int L = lane & 15;
        const int nr = L & 7, cb = (L >> 3) << 3;
        #pragma unroll
        for (int nt = 0; nt < 3; nt++) {
            const int n = w * 24 + nt * 8 + nr;
            #pragma unroll
            for (int kc = 0; kc < 5; kc++) {
                const uint32_t o = (uint32_t)(n * 176 + (kc * 16 + cb) * 2);
                LDSM_X2(bHi[nt][kc], sb + W_HI_ + o);
                LDSM_X2(bLo[nt][kc], sb + W_LO_ + o);
            }
        }
    }
    const int ccol = (lane & 3) * 2;
    const int mrow = lane >> 2;
    float bias_[3][2];
    #pragma unroll
    for (int nt = 0; nt < 3; nt++) {
        const int col = w * 24 + nt * 8 + ccol;
        bias_[nt][0] = b_ih[col] + b_hh[col];
        bias_[nt][1] = b_ih[col + 1] + b_hh[col + 1];
    }
    __syncthreads();     // W smem dead -> region becomes XP/GT

    float* XPf = (float*)(sm + XP_);
    float* GTf = (float*)(sm + GT_);

    // ---- prefetch xp(0) into XP buf 0 ----
    #pragma unroll
    for (int j = 0; j < 3; j++) {
        const int i = tid + LTHR * j;          // 1056 float4
        const int q = i / 66, e = i % 66;
        ((float4*)(XPf))[(q * 66) + e] =
            *(const float4*)(g_xproj + (size_t)(b0 + q) * G4 + e * 4);
    }
    __syncthreads();

    // cell state: 3 cells per thread
    float c_[3] = {0.f, 0.f, 0.f}, h_[3] = {0.f, 0.f, 0.f};

    for (int t = 0; t < T_; t++) {
        const int cur = t & 1, nxt = cur ^ 1;

        // A fragments for h(t)
        uint32_t aHi[5][4], aLo[5][4];
        {
            const int mat = lane >> 3, rr = lane & 7;
            const int row = ((mat & 1) << 3) + rr;
            const int cbA = (mat >> 1) << 3;
            #pragma unroll
            for (int kc = 0; kc < 5; kc++) {
                const uint32_t o = (uint32_t)(row * 176 + (kc * 16 + cbA) * 2);
                LDSM_X4(aHi[kc], sb + A_HI_ + o);
                LDSM_X4(aLo[kc], sb + A_LO_ + o);
            }
        }

        // prefetch xp(t+1) to regs (full step of latency cover)
        float4 pf[3];
        {
            const size_t tb = (size_t)((t + 1 < T_) ? t + 1 : t) * BG;
            #pragma unroll
            for (int j = 0; j < 3; j++) {
                const int i = tid + LTHR * j;
                const int q = i / 66, e = i % 66;
                pf[j] = *(const float4*)(g_xproj + tb + (size_t)(b0 + q) * G4 + e * 4);
            }
        }

        // MMA + activation per n-tile
        const float* XPc = XPf + cur * (LB * G4);
        #pragma unroll
        for (int nt = 0; nt < 3; nt++) {
            float c4[4] = {0.f, 0.f, 0.f, 0.f};
            #pragma unroll
            for (int kc = 0; kc < 5; kc++) {
                MMA_BF16(c4, aHi[kc], bHi[nt][kc]);
                MMA_BF16(c4, aHi[kc], bLo[nt][kc]);
                MMA_BF16(c4, aLo[kc], bHi[nt][kc]);
            }
            const int col0 = w * 24 + nt * 8 + ccol, col1 = col0 + 1;
            const float p00 = c4[0] + XPc[mrow * G4 + col0]       + bias_[nt][0];
            const float p01 = c4[1] + XPc[mrow * G4 + col1]       + bias_[nt][1];
            const float p10 = c4[2] + XPc[(mrow + 8) * G4 + col0] + bias_[nt][0];
            const float p11 = c4[3] + XPc[(mrow + 8) * G4 + col1] + bias_[nt][1];
            const bool tg0 = (col0 >= 2 * H_) && (col0 < 3 * H_);
            const bool tg1 = (col1 >= 2 * H_) && (col1 < 3 * H_);
            GTf[mrow * G4 + col0]       = tg0 ? (2.f * sigm_(2.f * p00) - 1.f) : sigm_(p00);
            GTf[mrow * G4 + col1]       = tg1 ? (2.f * sigm_(2.f * p01) - 1.f) : sigm_(p01);
            GTf[(mrow + 8) * G4 + col0] = tg0 ? (2.f * sigm_(2.f * p10) - 1.f) : sigm_(p10);
            GTf[(mrow + 8) * G4 + col1] = tg1 ? (2.f * sigm_(2.f * p11) - 1.f) : sigm_(p11);
        }

        // publish xp(t+1)
        #pragma unroll
        for (int j = 0; j < 3; j++) {
            const int i = tid + LTHR * j;
            const int q = i / 66, e = i % 66;
            ((float4*)(XPf + nxt * (LB * G4)))[(q * 66) + e] = pf[j];
        }
        __syncthreads();                    // gates + xp(t+1) visible

        // cell update: 3 cells per thread; write h(t+1) split into A smem
        #pragma unroll
        for (int j = 0; j < 3; j++) {
            const int cid = tid + LTHR * j;
            const int q = cid / H_, r = cid % H_;
            const float i_ = GTf[q * G4 + r];
            const float f_ = GTf[q * G4 + H_ + r];
            const float gg = GTf[q * G4 + 2 * H_ + r];
            const float o_ = GTf[q * G4 + 3 * H_ + r];
            c_[j] = f_ * c_[j] + i_ * gg;
            const float th = 2.f * sigm_(2.f * c_[j]) - 1.f;
            h_[j] = o_ * th;
            const __nv_bfloat16 hh = __float2bfloat16(h_[j]);
            const __nv_bfloat16 hl = __float2bfloat16(h_[j] - __bfloat162float(hh));
            *(unsigned short*)(sm + A_HI_ + q * 176 + r * 2) = __bfloat16_as_ushort(hh);
            *(unsigned short*)(sm + A_LO_ + q * 176 + r * 2) = __bfloat16_as_ushort(hl);
        }
        __syncthreads();                    // h(t+1) visible for next ldmatrix
    }

    // ---- publish h_T; elect last block ----
    #pragma unroll
    for (int j = 0; j < 3; j++) {
        const int cid = tid + LTHR * j;
        const int q = cid / H_, r = cid % H_;
        g_hT[(b0 + q) * H_ + r] = h_[j];
    }
    __threadfence();
    __syncthreads();
    if (tid == 0) {
        unsigned old = atomicAdd(&g_done, 1);
        s_last = (old == LNB - 1) ? 1u : 0u;
    }
    __syncthreads();
    if (!s_last) return;
    if (tid == 0) g_done = 0;               // reset for graph replay
    __threadfence();

    // ---- BN stats ----
    if (tid < G4) {
        const int qc = tid / H_, rr = tid % H_;
        float s = 0.f, qs = 0.f;
        for (int b = qc * (B_ / 4); b < (qc + 1) * (B_ / 4); b++) {
            const float v = g_hT[b * H_ + rr];
            s += v; qs += v * v;
        }
        GTf[tid] = s; GTf[G4 + tid] = qs;
    }
    __syncthreads();
    if (tid < H_) {
        const float S = GTf[tid] + GTf[H_ + tid] + GTf[2*H_ + tid] + GTf[3*H_ + tid];
        const float Q = GTf[G4 + tid] + GTf[G4 + H_ + tid] + GTf[G4 + 2*H_ + tid] + GTf[G4 + 3*H_ + tid];
        const float mean = S * (1.f / B_);
        const float var  = Q * (1.f / B_) - mean * mean;
        const float a    = gamma[tid] * rsqrtf(var + 1e-5f);
        s_a[tid] = a * fc_w[tid];
        s_b[tid] = (beta[tid] - mean * a) * fc_w[tid];
    }
    __syncthreads();

    // ---- head ----
    const float f0 = fc_b[0];
    for (int b = tid; b < B_; b += LTHR) {
        float acc = f0;
        #pragma unroll
        for (int jj = 0; jj < H_; jj++)
            acc += s_a[jj] * g_hT[b * H_ + jj] + s_b[jj];
        out[b] = acc;
    }
}

// ================= launch =================
extern "C" void kernel_launch(void* const* d_in, const int* in_sizes, int n_in,
                              void* d_out, int out_size)
{
    const float* x     = (const float*)d_in[0];
    const float* W_ih  = (const float*)d_in[1];
    const float* W_hh  = (const float*)d_in[2];
    const float* b_ih  = (const float*)d_in[3];
    const float* b_hh  = (const float*)d_in[4];
    const float* gamma = (const float*)d_in[5];
    const float* beta  = (const float*)d_in[6];
    const float* fc_w  = (const float*)d_in[7];
    const float* fc_b  = (const float*)d_in[8];
    float* out = (float*)d_out;

    static bool attr_set = false;
    if (!attr_set) {
        cudaFuncSetAttribute(proj_mma, cudaFuncAttributeMaxDynamicSharedMemorySize, PSM_TOT);
        cudaFuncSetAttribute(lstm_mma, cudaFuncAttributeMaxDynamicSharedMemorySize, LSM_TOT);
        attr_set = true;
    }

    proj_mma<<<B_ * (T_ / MT), 256, PSM_TOT>>>(x, W_ih);
    lstm_mma<<<LNB, LTHR, LSM_TOT>>>(W_hh, b_ih, b_hh, gamma, beta, fc_w, fc_b, out);
}

// round 14
// speedup vs baseline: 1.0219x; 1.0219x over previous
#include <cuda_runtime.h>
#include <cuda_bf16.h>
#include <cstdint>

#define B_    512
#define T_    2048
#define D_    64
#define H_    66
#define G4    264
#define BG    (B_ * G4)          // x_proj stride per t: [T][B][G4]
#define MT    128                // t-rows per proj block
#define PADW  72                 // proj smem row pad (bf16)
// lstm_mma config
#define LB    16                 // batches per lstm block
#define LNB   (B_ / LB)          // 32 blocks
#define LTHR  352                // 11 warps: 3 n8-tiles each (33 total)
#define KP    88                 // padded K row (bf16) -> 176B stride

__device__ float    g_xproj[(size_t)T_ * B_ * G4];   // raw GEMM (no bias)
__device__ float    g_hT[B_ * H_];
__device__ unsigned g_done = 0;

__device__ __forceinline__ float sigm_(float x) {
    return __fdividef(1.f, 1.f + __expf(-x));
}

// ================= mma.sync helpers =================
__device__ __forceinline__ uint32_t smem_u32(const void* p) {
    uint32_t a;
    asm("{ .reg .u64 t; cvta.to.shared.u64 t, %1; cvt.u32.u64 %0, t; }" : "=r"(a) : "l"(p));
    return a;
}
#define LDSM_X4(r, a) \
    asm volatile("ldmatrix.sync.aligned.m8n8.x4.shared.b16 {%0,%1,%2,%3}, [%4];" \
        : "=r"((r)[0]),"=r"((r)[1]),"=r"((r)[2]),"=r"((r)[3]) : "r"(a))
#define LDSM_X2(r, a) \
    asm volatile("ldmatrix.sync.aligned.m8n8.x2.shared.b16 {%0,%1}, [%2];" \
        : "=r"((r)[0]),"=r"((r)[1]) : "r"(a))
#define MMA_BF16(d, a, bb) \
    asm volatile("mma.sync.aligned.m16n8k16.row.col.f32.bf16.bf16.f32 " \
        "{%0,%1,%2,%3}, {%4,%5,%6,%7}, {%8,%9}, {%0,%1,%2,%3};" \
        : "+f"((d)[0]),"+f"((d)[1]),"+f"((d)[2]),"+f"((d)[3]) \
        : "r"((a)[0]),"r"((a)[1]),"r"((a)[2]),"r"((a)[3]), "r"((bb)[0]),"r"((bb)[1]))

__device__ __forceinline__ uint32_t pack_bf16(__nv_bfloat16 lo, __nv_bfloat16 hi) {
    return ((uint32_t)__bfloat16_as_ushort(hi) << 16) | (uint32_t)__bfloat16_as_ushort(lo);
}
__device__ __forceinline__ void split_f4(float4 v, uint2& h, uint2& l) {
    const __nv_bfloat16 h0 = __float2bfloat16(v.x), h1 = __float2bfloat16(v.y),
                        h2 = __float2bfloat16(v.z), h3 = __float2bfloat16(v.w);
    h.x = pack_bf16(h0, h1); h.y = pack_bf16(h2, h3);
    l.x = pack_bf16(__float2bfloat16(v.x - __bfloat162float(h0)),
                    __float2bfloat16(v.y - __bfloat162float(h1)));
    l.y = pack_bf16(__float2bfloat16(v.z - __bfloat162float(h2)),
                    __float2bfloat16(v.w - __bfloat162float(h3)));
}

// ================= projection (R11, validated) =================
#define XS_HI 0
#define XS_LO (XS_HI + MT * PADW * 2)
#define WS_HI (XS_LO + MT * PADW * 2)
#define WS_LO (WS_HI + G4 * PADW * 2)
#define PSM_TOT (WS_LO + G4 * PADW * 2)

__global__ __launch_bounds__(256, 1) void proj_mma(const float* __restrict__ x,
                                                   const float* __restrict__ W_ih)
{
    extern __shared__ __align__(16) char smem[];
    const uint32_t sb = smem_u32(smem);
    const int tid  = threadIdx.x;
    const int w    = tid >> 5, lane = tid & 31;
    const int b    = blockIdx.x >> 4;
    const int t0   = (blockIdx.x & 15) * MT;

    {
        const float4* wg = (const float4*)W_ih;
        for (int i = tid; i < G4 * (D_ / 4); i += 256) {
            const int row = i >> 4, c4 = (i & 15) * 4;
            uint2 h, l; split_f4(wg[i], h, l);
            const uint32_t off = (uint32_t)(row * PADW + c4) * 2;
            *(uint2*)(smem + WS_HI + off) = h;
            *(uint2*)(smem + WS_LO + off) = l;
        }
    }
    {
        const float4* xg = (const float4*)(x + ((size_t)b * T_ + t0) * D_);
        for (int i = tid; i < MT * (D_ / 4); i += 256) {
            const int row = i >> 4, c4 = (i & 15) * 4;
            uint2 h, l; split_f4(xg[i], h, l);
            const uint32_t off = (uint32_t)(row * PADW + c4) * 2;
            *(uint2*)(smem + XS_HI + off) = h;
            *(uint2*)(smem + XS_LO + off) = l;
        }
    }
    __syncthreads();

    uint32_t aHi[4][4], aLo[4][4];
    {
        const int mat = lane >> 3, r = lane & 7;
        const int row = 16 * w + ((mat & 1) << 3) + r;
        const int colb = (mat >> 1) << 3;
        #pragma unroll
        for (int kc = 0; kc < 4; kc++) {
            const uint32_t o = (uint32_t)(row * PADW + kc * 16 + colb) * 2;
            LDSM_X4(aHi[kc], sb + XS_HI + o);
            LDSM_X4(aLo[kc], sb + XS_LO + o);
        }
    }

    const int L = lane & 15;
    const int nr   = L & 7;
    const int colb = (L >> 3) << 3;
    const int mrow = lane >> 2;
    const int ccol = (lane & 3) * 2;

    for (int nt = 0; nt < 33; nt++) {
        uint32_t bHi[4][2], bLo[4][2];
        const int n = nt * 8 + nr;
        #pragma unroll
        for (int kc = 0; kc < 4; kc++) {
            const uint32_t o = (uint32_t)(n * PADW + kc * 16 + colb) * 2;
            LDSM_X2(bHi[kc], sb + WS_HI + o);
            LDSM_X2(bLo[kc], sb + WS_LO + o);
        }
        float c[4] = {0.f, 0.f, 0.f, 0.f};
        #pragma unroll
        for (int kc = 0; kc < 4; kc++) {
            MMA_BF16(c, aHi[kc], bHi[kc]);
            MMA_BF16(c, aHi[kc], bLo[kc]);
            MMA_BF16(c, aLo[kc], bHi[kc]);
        }
        float* op = g_xproj + (size_t)(t0 + 16 * w + mrow) * BG
                  + (size_t)b * G4 + nt * 8 + ccol;
        *(float2*)op                      = make_float2(c[0], c[1]);
        *(float2*)(op + (size_t)8 * BG)   = make_float2(c[2], c[3]);
    }
}

// ================= recurrence on HMMA (pipelined xp, split accumulators) =================
#define A_HI_  0
#define A_LO_  (LB * 176)                 // 2816
#define UNI_   (2 * LB * 176)             // 5632
#define W_HI_  (UNI_)
#define W_LO_  (UNI_ + G4 * 176)
#define XP_    (UNI_)                     // 2 * 16*264*4 = 33792
#define GT_    (UNI_ + 2 * LB * G4 * 4)
#define LSM_TOT (UNI_ + 2 * G4 * 176)     // 98560

__global__ __launch_bounds__(LTHR, 1) void lstm_mma(
    const float* __restrict__ W_hh,  const float* __restrict__ b_ih,
    const float* __restrict__ b_hh,  const float* __restrict__ gamma,
    const float* __restrict__ beta,  const float* __restrict__ fc_w,
    const float* __restrict__ fc_b,  float* __restrict__ out)
{
    extern __shared__ __align__(16) char sm[];
    const uint32_t sb = smem_u32(sm);
    const int tid = threadIdx.x, w = tid >> 5, lane = tid & 31;
    const int b0  = blockIdx.x * LB;
    __shared__ unsigned s_last;
    __shared__ float s_a[H_], s_b[H_];

    // ---- zero A (h = 0, incl. k-pad) ----
    for (int i = tid; i < UNI_ / 4; i += LTHR) ((uint32_t*)sm)[i] = 0;

    // ---- split W_hh -> W smem (bf16 hi/lo, k-padded) ----
    for (int i = tid; i < G4 * KP; i += LTHR) {
        const int row = i / KP, col = i % KP;
        const float v = (col < H_) ? W_hh[row * H_ + col] : 0.f;
        const __nv_bfloat16 hi = __float2bfloat16(v);
        const __nv_bfloat16 lo = __float2bfloat16(v - __bfloat162float(hi));
        *(unsigned short*)(sm + W_HI_ + row * 176 + col * 2) = __bfloat16_as_ushort(hi);
        *(unsigned short*)(sm + W_LO_ + row * 176 + col * 2) = __bfloat16_as_ushort(lo);
    }
    __syncthreads();

    // ---- persistent B fragments: 3 n8-tiles per warp ----
    uint32_t bHi[3][5][2], bLo[3][5][2];
    {
        const int L = lane & 15;
        const int nr = L & 7, cb = (L >> 3) << 3;
        #pragma unroll
        for (int nt = 0; nt < 3; nt++) {
            const int n = w * 24 + nt * 8 + nr;
            #pragma unroll
            for (int kc = 0; kc < 5; kc++) {
                const uint32_t o = (uint32_t)(n * 176 + (kc * 16 + cb) * 2);
                LDSM_X2(bHi[nt][kc], sb + W_HI_ + o);
                LDSM_X2(bLo[nt][kc], sb + W_LO_ + o);
            }
        }
    }
    const int ccol = (lane & 3) * 2;
    const int mrow = lane >> 2;
    float bias_[3][2];
    #pragma unroll
    for (int nt = 0; nt < 3; nt++) {
        const int col = w * 24 + nt * 8 + ccol;
        bias_[nt][0] = b_ih[col] + b_hh[col];
        bias_[nt][1] = b_ih[col + 1] + b_hh[col + 1];
    }
    __syncthreads();     // W smem dead -> region becomes XP/GT

    float* XPf = (float*)(sm + XP_);
    float* GTf = (float*)(sm + GT_);

    // ---- prologue: xp(0) -> XP buf 0 directly; xp(1) -> pf regs ----
    #pragma unroll
    for (int j = 0; j < 3; j++) {
        const int i = tid + LTHR * j;          // 1056 float4
        const int q = i / 66, e = i % 66;
        ((float4*)XPf)[(q * 66) + e] =
            *(const float4*)(g_xproj + (size_t)(b0 + q) * G4 + e * 4);
    }
    float4 pf[3];
    #pragma unroll
    for (int j = 0; j < 3; j++) {
        const int i = tid + LTHR * j;
        const int q = i / 66, e = i % 66;
        pf[j] = *(const float4*)(g_xproj + (size_t)1 * BG + (size_t)(b0 + q) * G4 + e * 4);
    }
    __syncthreads();

    float c_[3] = {0.f, 0.f, 0.f}, h_[3] = {0.f, 0.f, 0.f};

    for (int t = 0; t < T_; t++) {
        const int cur = t & 1, nxt = cur ^ 1;

        // 1) publish xp(t+1) from pf (loaded LAST step -> no DRAM dependency here)
        #pragma unroll
        for (int j = 0; j < 3; j++) {
            const int i = tid + LTHR * j;
            const int q = i / 66, e = i % 66;
            ((float4*)(XPf + nxt * (LB * G4)))[(q * 66) + e] = pf[j];
        }
        // 2) issue load of xp(t+2) -> pf (covered by this whole step)
        {
            const int tn = (t + 2 < T_) ? (t + 2) : (T_ - 1);
            const size_t tb = (size_t)tn * BG;
            #pragma unroll
            for (int j = 0; j < 3; j++) {
                const int i = tid + LTHR * j;
                const int q = i / 66, e = i % 66;
                pf[j] = *(const float4*)(g_xproj + tb + (size_t)(b0 + q) * G4 + e * 4);
            }
        }

        // 3) A fragments for h(t)
        uint32_t aHi[5][4], aLo[5][4];
        {
            const int mat = lane >> 3, rr = lane & 7;
            const int row = ((mat & 1) << 3) + rr;
            const int cbA = (mat >> 1) << 3;
            #pragma unroll
            for (int kc = 0; kc < 5; kc++) {
                const uint32_t o = (uint32_t)(row * 176 + (kc * 16 + cbA) * 2);
                LDSM_X4(aHi[kc], sb + A_HI_ + o);
                LDSM_X4(aLo[kc], sb + A_LO_ + o);
            }
        }

        // 4) MMA per n-tile: 3 independent accumulators (chain 5, not 15)
        const float* XPc = XPf + cur * (LB * G4);
        #pragma unroll
        for (int nt = 0; nt < 3; nt++) {
            float cA[4] = {0.f, 0.f, 0.f, 0.f};
            float cB[4] = {0.f, 0.f, 0.f, 0.f};
            float cC[4] = {0.f, 0.f, 0.f, 0.f};
            #pragma unroll
            for (int kc = 0; kc < 5; kc++) {
                MMA_BF16(cA, aHi[kc], bHi[nt][kc]);
                MMA_BF16(cB, aHi[kc], bLo[nt][kc]);
                MMA_BF16(cC, aLo[kc], bHi[nt][kc]);
            }
            const int col0 = w * 24 + nt * 8 + ccol, col1 = col0 + 1;
            const float p00 = (cA[0] + cB[0] + cC[0]) + XPc[mrow * G4 + col0]       + bias_[nt][0];
            const float p01 = (cA[1] + cB[1] + cC[1]) + XPc[mrow * G4 + col1]       + bias_[nt][1];
            const float p10 = (cA[2] + cB[2] + cC[2]) + XPc[(mrow + 8) * G4 + col0] + bias_[nt][0];
            const float p11 = (cA[3] + cB[3] + cC[3]) + XPc[(mrow + 8) * G4 + col1] + bias_[nt][1];
            const bool tg0 = (col0 >= 2 * H_) && (col0 < 3 * H_);
            const bool tg1 = (col1 >= 2 * H_) && (col1 < 3 * H_);
            GTf[mrow * G4 + col0]       = tg0 ? (2.f * sigm_(2.f * p00) - 1.f) : sigm_(p00);
            GTf[mrow * G4 + col1]       = tg1 ? (2.f * sigm_(2.f * p01) - 1.f) : sigm_(p01);
            GTf[(mrow + 8) * G4 + col0] = tg0 ? (2.f * sigm_(2.f * p10) - 1.f) : sigm_(p10);
            GTf[(mrow + 8) * G4 + col1] = tg1 ? (2.f * sigm_(2.f * p11) - 1.f) : sigm_(p11);
        }
        __syncthreads();                    // gates + xp(t+1) visible

        // 5) cell update: 3 cells per thread; write h(t+1) split into A smem
        #pragma unroll
        for (int j = 0; j < 3; j++) {
            const int cid = tid + LTHR * j;
            const int q = cid / H_, r = cid % H_;
            const float i_ = GTf[q * G4 + r];
            const float f_ = GTf[q * G4 + H_ + r];
            const float gg = GTf[q * G4 + 2 * H_ + r];
            const float o_ = GTf[q * G4 + 3 * H_ + r];
            c_[j] = f_ * c_[j] + i_ * gg;
            const float th = 2.f * sigm_(2.f * c_[j]) - 1.f;
            h_[j] = o_ * th;
            const __nv_bfloat16 hh = __float2bfloat16(h_[j]);
            const __nv_bfloat16 hl = __float2bfloat16(h_[j] - __bfloat162float(hh));
            *(unsigned short*)(sm + A_HI_ + q * 176 + r * 2) = __bfloat16_as_ushort(hh);
            *(unsigned short*)(sm + A_LO_ + q * 176 + r * 2) = __bfloat16_as_ushort(hl);
        }
        __syncthreads();                    // h(t+1) visible for next ldmatrix
    }

    // ---- publish h_T; elect last block ----
    #pragma unroll
    for (int j = 0; j < 3; j++) {
        const int cid = tid + LTHR * j;
        const int q = cid / H_, r = cid % H_;
        g_hT[(b0 + q) * H_ + r] = h_[j];
    }
    __threadfence();
    __syncthreads();
    if (tid == 0) {
        unsigned old = atomicAdd(&g_done, 1);
        s_last = (old == LNB - 1) ? 1u : 0u;
    }
    __syncthreads();
    if (!s_last) return;
    if (tid == 0) g_done = 0;               // reset for graph replay
    __threadfence();

    // ---- BN stats ----
    if (tid < G4) {
        const int qc = tid / H_, rr = tid % H_;
        float s = 0.f, qs = 0.f;
        for (int b = qc * (B_ / 4); b < (qc + 1) * (B_ / 4); b++) {
            const float v = g_hT[b * H_ + rr];
            s += v; qs += v * v;
        }
        GTf[tid] = s; GTf[G4 + tid] = qs;
    }
    __syncthreads();
    if (tid < H_) {
        const float S = GTf[tid] + GTf[H_ + tid] + GTf[2*H_ + tid] + GTf[3*H_ + tid];
        const float Q = GTf[G4 + tid] + GTf[G4 + H_ + tid] + GTf[G4 + 2*H_ + tid] + GTf[G4 + 3*H_ + tid];
        const float mean = S * (1.f / B_);
        const float var  = Q * (1.f / B_) - mean * mean;
        const float a    = gamma[tid] * rsqrtf(var + 1e-5f);
        s_a[tid] = a * fc_w[tid];
        s_b[tid] = (beta[tid] - mean * a) * fc_w[tid];
    }
    __syncthreads();

    // ---- head ----
    const float f0 = fc_b[0];
    for (int b = tid; b < B_; b += LTHR) {
        float acc = f0;
        #pragma unroll
        for (int jj = 0; jj < H_; jj++)
            acc += s_a[jj] * g_hT[b * H_ + jj] + s_b[jj];
        out[b] = acc;
    }
}

// ================= launch =================
extern "C" void kernel_launch(void* const* d_in, const int* in_sizes, int n_in,
                              void* d_out, int out_size)
{
    const float* x     = (const float*)d_in[0];
    const float* W_ih  = (const float*)d_in[1];
    const float* W_hh  = (const float*)d_in[2];
    const float* b_ih  = (const float*)d_in[3];
    const float* b_hh  = (const float*)d_in[4];
    const float* gamma = (const float*)d_in[5];
    const float* beta  = (const float*)d_in[6];
    const float* fc_w  = (const float*)d_in[7];
    const float* fc_b  = (const float*)d_in[8];
    float* out = (float*)d_out;

    static bool attr_set = false;
    if (!attr_set) {
        cudaFuncSetAttribute(proj_mma, cudaFuncAttributeMaxDynamicSharedMemorySize, PSM_TOT);
        cudaFuncSetAttribute(lstm_mma, cudaFuncAttributeMaxDynamicSharedMemorySize, LSM_TOT);
        attr_set = true;
    }

    proj_mma<<<B_ * (T_ / MT), 256, PSM_TOT>>>(x, W_ih);
    lstm_mma<<<LNB, LTHR, LSM_TOT>>>(W_hh, b_ih, b_hh, gamma, beta, fc_w, fc_b, out);
}

// round 15
// speedup vs baseline: 1.2386x; 1.2121x over previous
#include <cuda_runtime.h>
#include <cuda_bf16.h>
#include <cstdint>

#define B_    512
#define T_    2048
#define D_    64
#define H_    66
#define G4    264
#define BG    (B_ * G4)          // x_proj stride per t: [T][B][G4]
#define MT    128                // t-rows per proj block
#define PADW  72                 // proj smem row pad (bf16)
// lstm_mma config
#define LB    16                 // batches per lstm block
#define LNB   (B_ / LB)          // 32 blocks
#define LTHR  352                // 11 warps: 3 n8-tiles each
#define KP    88                 // padded K row (bf16) -> 176B stride

// gate-row permutation: smem/xproj column p <- original gate row orig(p)
// p = 4*cell + k, k in {0:i, 1:f, 2:g, 3:o};  orig(p) = k*66 + cell
#define ORIG(p) (((p) & 3) * H_ + ((p) >> 2))

__device__ float    g_xproj[(size_t)T_ * B_ * G4];   // [T][B][G4], permuted cols
__device__ float    g_hT[B_ * H_];
__device__ unsigned g_done = 0;

__device__ __forceinline__ float sigm_(float x) {
    return __fdividef(1.f, 1.f + __expf(-x));
}
__device__ __forceinline__ float tanh_(float x) {
    return 2.f * __fdividef(1.f, 1.f + __expf(-2.f * x)) - 1.f;
}

// ================= mma.sync helpers =================
__device__ __forceinline__ uint32_t smem_u32(const void* p) {
    uint32_t a;
    asm("{ .reg .u64 t; cvta.to.shared.u64 t, %1; cvt.u32.u64 %0, t; }" : "=r"(a) : "l"(p));
    return a;
}
#define LDSM_X4(r, a) \
    asm volatile("ldmatrix.sync.aligned.m8n8.x4.shared.b16 {%0,%1,%2,%3}, [%4];" \
        : "=r"((r)[0]),"=r"((r)[1]),"=r"((r)[2]),"=r"((r)[3]) : "r"(a))
#define LDSM_X2(r, a) \
    asm volatile("ldmatrix.sync.aligned.m8n8.x2.shared.b16 {%0,%1}, [%2];" \
        : "=r"((r)[0]),"=r"((r)[1]) : "r"(a))
#define MMA_BF16(d, a, bb) \
    asm volatile("mma.sync.aligned.m16n8k16.row.col.f32.bf16.bf16.f32 " \
        "{%0,%1,%2,%3}, {%4,%5,%6,%7}, {%8,%9}, {%0,%1,%2,%3};" \
        : "+f"((d)[0]),"+f"((d)[1]),"+f"((d)[2]),"+f"((d)[3]) \
        : "r"((a)[0]),"r"((a)[1]),"r"((a)[2]),"r"((a)[3]), "r"((bb)[0]),"r"((bb)[1]))

__device__ __forceinline__ uint32_t pack_bf16(__nv_bfloat16 lo, __nv_bfloat16 hi) {
    return ((uint32_t)__bfloat16_as_ushort(hi) << 16) | (uint32_t)__bfloat16_as_ushort(lo);
}
__device__ __forceinline__ void split_f4(float4 v, uint2& h, uint2& l) {
    const __nv_bfloat16 h0 = __float2bfloat16(v.x), h1 = __float2bfloat16(v.y),
                        h2 = __float2bfloat16(v.z), h3 = __float2bfloat16(v.w);
    h.x = pack_bf16(h0, h1); h.y = pack_bf16(h2, h3);
    l.x = pack_bf16(__float2bfloat16(v.x - __bfloat162float(h0)),
                    __float2bfloat16(v.y - __bfloat162float(h1)));
    l.y = pack_bf16(__float2bfloat16(v.z - __bfloat162float(h2)),
                    __float2bfloat16(v.w - __bfloat162float(h3)));
}

// ================= projection (R11 validated + gate-row permutation) =================
#define XS_HI 0
#define XS_LO (XS_HI + MT * PADW * 2)
#define WS_HI (XS_LO + MT * PADW * 2)
#define WS_LO (WS_HI + G4 * PADW * 2)
#define PSM_TOT (WS_LO + G4 * PADW * 2)

__global__ __launch_bounds__(256, 1) void proj_mma(const float* __restrict__ x,
                                                   const float* __restrict__ W_ih)
{
    extern __shared__ __align__(16) char smem[];
    const uint32_t sb = smem_u32(smem);
    const int tid  = threadIdx.x;
    const int w    = tid >> 5, lane = tid & 31;
    const int b    = blockIdx.x >> 4;
    const int t0   = (blockIdx.x & 15) * MT;

    {
        const float4* wg = (const float4*)W_ih;
        for (int i = tid; i < G4 * (D_ / 4); i += 256) {
            const int row = i >> 4, c4 = (i & 15) * 4;     // row = permuted col p
            uint2 h, l; split_f4(wg[ORIG(row) * 16 + (i & 15)], h, l);
            const uint32_t off = (uint32_t)(row * PADW + c4) * 2;
            *(uint2*)(smem + WS_HI + off) = h;
            *(uint2*)(smem + WS_LO + off) = l;
        }
    }
    {
        const float4* xg = (const float4*)(x + ((size_t)b * T_ + t0) * D_);
        for (int i = tid; i < MT * (D_ / 4); i += 256) {
            const int row = i >> 4, c4 = (i & 15) * 4;
            uint2 h, l; split_f4(xg[i], h, l);
            const uint32_t off = (uint32_t)(row * PADW + c4) * 2;
            *(uint2*)(smem + XS_HI + off) = h;
            *(uint2*)(smem + XS_LO + off) = l;
        }
    }
    __syncthreads();

    uint32_t aHi[4][4], aLo[4][4];
    {
        const int mat = lane >> 3, r = lane & 7;
        const int row = 16 * w + ((mat & 1) << 3) + r;
        const int colb = (mat >> 1) << 3;
        #pragma unroll
        for (int kc = 0; kc < 4; kc++) {
            const uint32_t o = (uint32_t)(row * PADW + kc * 16 + colb) * 2;
            LDSM_X4(aHi[kc], sb + XS_HI + o);
            LDSM_X4(aLo[kc], sb + XS_LO + o);
        }
    }

    const int L = lane & 15;
    const int nr   = L & 7;
    const int colb = (L >> 3) << 3;
    const int mrow = lane >> 2;
    const int ccol = (lane & 3) * 2;

    for (int nt = 0; nt < 33; nt++) {
        uint32_t bHi[4][2], bLo[4][2];
        const int n = nt * 8 + nr;
        #pragma unroll
        for (int kc = 0; kc < 4; kc++) {
            const uint32_t o = (uint32_t)(n * PADW + kc * 16 + colb) * 2;
            LDSM_X2(bHi[kc], sb + WS_HI + o);
            LDSM_X2(bLo[kc], sb + WS_LO + o);
        }
        float c[4] = {0.f, 0.f, 0.f, 0.f};
        #pragma unroll
        for (int kc = 0; kc < 4; kc++) {
            MMA_BF16(c, aHi[kc], bHi[kc]);
            MMA_BF16(c, aHi[kc], bLo[kc]);
            MMA_BF16(c, aLo[kc], bHi[kc]);
        }
        float* op = g_xproj + (size_t)(t0 + 16 * w + mrow) * BG
                  + (size_t)b * G4 + nt * 8 + ccol;
        *(float2*)op                      = make_float2(c[0], c[1]);
        *(float2*)(op + (size_t)8 * BG)   = make_float2(c[2], c[3]);
    }
}

// ================= recurrence: 1 barrier/step, shfl cell-update =================
// smem: A double-buffered (h bf16 hi/lo), then W region (reused for BN scratch)
#define ABUF   5632                       // one A buffer: hi 2816 + lo 2816
#define UNI_   (2 * ABUF)                 // 11264
#define W_HI_  (UNI_)
#define W_LO_  (UNI_ + G4 * 176)
#define LSM_TOT (UNI_ + 2 * G4 * 176)     // 104192

__global__ __launch_bounds__(LTHR, 1) void lstm_mma(
    const float* __restrict__ W_hh,  const float* __restrict__ b_ih,
    const float* __restrict__ b_hh,  const float* __restrict__ gamma,
    const float* __restrict__ beta,  const float* __restrict__ fc_w,
    const float* __restrict__ fc_b,  float* __restrict__ out)
{
    extern __shared__ __align__(16) char sm[];
    const uint32_t sb = smem_u32(sm);
    const int tid = threadIdx.x, w = tid >> 5, lane = tid & 31;
    const int b0  = blockIdx.x * LB;
    __shared__ unsigned s_last;
    __shared__ float s_a[H_], s_b[H_];

    // ---- zero both A buffers (h = 0, incl. k-pad) ----
    for (int i = tid; i < UNI_ / 4; i += LTHR) ((uint32_t*)sm)[i] = 0;

    // ---- split W_hh -> W smem (bf16 hi/lo, permuted rows, k-padded) ----
    for (int i = tid; i < G4 * KP; i += LTHR) {
        const int row = i / KP, col = i % KP;          // row = permuted col p
        const float v = (col < H_) ? W_hh[ORIG(row) * H_ + col] : 0.f;
        const __nv_bfloat16 hi = __float2bfloat16(v);
        const __nv_bfloat16 lo = __float2bfloat16(v - __bfloat162float(hi));
        *(unsigned short*)(sm + W_HI_ + row * 176 + col * 2) = __bfloat16_as_ushort(hi);
        *(unsigned short*)(sm + W_LO_ + row * 176 + col * 2) = __bfloat16_as_ushort(lo);
    }
    __syncthreads();

    // ---- persistent B fragments: 3 n8-tiles per warp ----
    uint32_t bHi[3][5][2], bLo[3][5][2];
    {
        const int L = lane & 15;
        const int nr = L & 7, cb = (L >> 3) << 3;
        #pragma unroll
        for (int nt = 0; nt < 3; nt++) {
            const int n = w * 24 + nt * 8 + nr;
            #pragma unroll
            for (int kc = 0; kc < 5; kc++) {
                const uint32_t o = (uint32_t)(n * 176 + (kc * 16 + cb) * 2);
                LDSM_X2(bHi[nt][kc], sb + W_HI_ + o);
                LDSM_X2(bLo[nt][kc], sb + W_LO_ + o);
            }
        }
    }
    const int ccol = (lane & 3) * 2;
    const int mrow = lane >> 2;
    const int odd  = lane & 1;                 // 0: (i,f) cols, updates row mrow
                                               // 1: (g,o) cols, updates row mrow+8
    const int myrow = mrow + 8 * odd;
    float bias_[3][2];
    int   cell_[3];
    #pragma unroll
    for (int nt = 0; nt < 3; nt++) {
        const int col = w * 24 + nt * 8 + ccol;
        bias_[nt][0] = b_ih[ORIG(col)]     + b_hh[ORIG(col)];
        bias_[nt][1] = b_ih[ORIG(col + 1)] + b_hh[ORIG(col + 1)];
        cell_[nt]    = col >> 2;               // 6w + 2nt + ((lane>>1)&1)
    }
    __syncthreads();

    // ---- prologue: xp(0) -> pf regs (fragment-matched layout) ----
    float2 pf[6];
    #pragma unroll
    for (int nt = 0; nt < 3; nt++) {
        const int col = w * 24 + nt * 8 + ccol;
        pf[2*nt]   = *(const float2*)(g_xproj + (size_t)(b0 + mrow)     * G4 + col);
        pf[2*nt+1] = *(const float2*)(g_xproj + (size_t)(b0 + mrow + 8) * G4 + col);
    }

    float c_[3] = {0.f, 0.f, 0.f}, h_[3] = {0.f, 0.f, 0.f};

    for (int t = 0; t < T_; t++) {
        const uint32_t cur = (t & 1) * ABUF, nxt = ((t + 1) & 1) * ABUF;

        // issue xp(t+1) loads early (covered by entire step)
        float2 pfn[6];
        {
            const size_t tb = (size_t)((t + 1 < T_) ? t + 1 : t) * BG;
            #pragma unroll
            for (int nt = 0; nt < 3; nt++) {
                const int col = w * 24 + nt * 8 + ccol;
                pfn[2*nt]   = *(const float2*)(g_xproj + tb + (size_t)(b0 + mrow)     * G4 + col);
                pfn[2*nt+1] = *(const float2*)(g_xproj + tb + (size_t)(b0 + mrow + 8) * G4 + col);
            }
        }

        // A fragments for h(t) from buffer cur
        uint32_t aHi[5][4], aLo[5][4];
        {
            const int mat = lane >> 3, rr = lane & 7;
            const int row = ((mat & 1) << 3) + rr;
            const int cbA = (mat >> 1) << 3;
            #pragma unroll
            for (int kc = 0; kc < 5; kc++) {
                const uint32_t o = (uint32_t)(row * 176 + (kc * 16 + cbA) * 2);
                LDSM_X4(aHi[kc], sb + cur + o);
                LDSM_X4(aLo[kc], sb + cur + 2816 + o);
            }
        }

        // per n-tile: MMA -> activation -> shfl exchange -> cell update -> STS h
        #pragma unroll
        for (int nt = 0; nt < 3; nt++) {
            float cA[4] = {0.f,0.f,0.f,0.f}, cB[4] = {0.f,0.f,0.f,0.f}, cC[4] = {0.f,0.f,0.f,0.f};
            #pragma unroll
            for (int kc = 0; kc < 5; kc++) {
                MMA_BF16(cA, aHi[kc], bHi[nt][kc]);
                MMA_BF16(cB, aHi[kc], bLo[nt][kc]);
                MMA_BF16(cC, aLo[kc], bHi[nt][kc]);
            }
            const float p00 = (cA[0]+cB[0]+cC[0]) + pf[2*nt].x   + bias_[nt][0];
            const float p01 = (cA[1]+cB[1]+cC[1]) + pf[2*nt].y   + bias_[nt][1];
            const float p10 = (cA[2]+cB[2]+cC[2]) + pf[2*nt+1].x + bias_[nt][0];
            const float p11 = (cA[3]+cB[3]+cC[3]) + pf[2*nt+1].y + bias_[nt][1];

            // activation: even lanes hold (i,f) -> sigmoid; odd hold (g,o) -> (tanh, sigmoid)
            float a0, a1, a2, a3;
            if (!odd) { a0 = sigm_(p00); a2 = sigm_(p10); }
            else      { a0 = tanh_(p00); a2 = tanh_(p10); }
            a1 = sigm_(p01);
            a3 = sigm_(p11);

            // exchange with partner lane (lane^1)
            const float r0 = __shfl_xor_sync(0xffffffffu, a0, 1);
            const float r1 = __shfl_xor_sync(0xffffffffu, a1, 1);
            const float r2 = __shfl_xor_sync(0xffffffffu, a2, 1);
            const float r3 = __shfl_xor_sync(0xffffffffu, a3, 1);

            // even lane updates row mrow:   i=a0 f=a1 g=r0 o=r1
            // odd  lane updates row mrow+8: i=r2 f=r3 g=a2 o=a3
            const float i_ = odd ? r2 : a0;
            const float f_ = odd ? r3 : a1;
            const float g_ = odd ? a2 : r0;
            const float o_ = odd ? a3 : r1;
            c_[nt] = f_ * c_[nt] + i_ * g_;
            h_[nt] = o_ * tanh_(c_[nt]);

            const __nv_bfloat16 hh = __float2bfloat16(h_[nt]);
            const __nv_bfloat16 hl = __float2bfloat16(h_[nt] - __bfloat162float(hh));
            const uint32_t ho = (uint32_t)(myrow * 176 + cell_[nt] * 2);
            *(unsigned short*)(sm + nxt + ho)        = __bfloat16_as_ushort(hh);
            *(unsigned short*)(sm + nxt + 2816 + ho) = __bfloat16_as_ushort(hl);
        }

        #pragma unroll
        for (int j = 0; j < 6; j++) pf[j] = pfn[j];
        __syncthreads();                   // h(t+1) published; also fences next LDSM vs this STS
    }

    // ---- publish h_T; elect last block ----
    #pragma unroll
    for (int nt = 0; nt < 3; nt++)
        g_hT[(b0 + myrow) * H_ + cell_[nt]] = h_[nt];
    __threadfence();
    __syncthreads();
    if (tid == 0) {
        unsigned old = atomicAdd(&g_done, 1);
        s_last = (old == LNB - 1) ? 1u : 0u;
    }
    __syncthreads();
    if (!s_last) return;
    if (tid == 0) g_done = 0;               // reset for graph replay
    __threadfence();

    // ---- BN stats (scratch in dead W region) ----
    float* GTf = (float*)(sm + UNI_);
    if (tid < G4) {
        const int qc = tid / H_, rr = tid % H_;
        float s = 0.f, qs = 0.f;
        for (int b = qc * (B_ / 4); b < (qc + 1) * (B_ / 4); b++) {
            const float v = g_hT[b * H_ + rr];
            s += v; qs += v * v;
        }
        GTf[tid] = s; GTf[G4 + tid] = qs;
    }
    __syncthreads();
    if (tid < H_) {
        const float S = GTf[tid] + GTf[H_ + tid] + GTf[2*H_ + tid] + GTf[3*H_ + tid];
        const float Q = GTf[G4 + tid] + GTf[G4 + H_ + tid] + GTf[G4 + 2*H_ + tid] + GTf[G4 + 3*H_ + tid];
        const float mean = S * (1.f / B_);
        const float var  = Q * (1.f / B_) - mean * mean;
        const float a    = gamma[tid] * rsqrtf(var + 1e-5f);
        s_a[tid] = a * fc_w[tid];
        s_b[tid] = (beta[tid] - mean * a) * fc_w[tid];
    }
    __syncthreads();

    // ---- head ----
    const float f0 = fc_b[0];
    for (int b = tid; b < B_; b += LTHR) {
        float acc = f0;
        #pragma unroll
        for (int jj = 0; jj < H_; jj++)
            acc += s_a[jj] * g_hT[b * H_ + jj] + s_b[jj];
        out[b] = acc;
    }
}

// ================= launch =================
extern "C" void kernel_launch(void* const* d_in, const int* in_sizes, int n_in,
                              void* d_out, int out_size)
{
    const float* x     = (const float*)d_in[0];
    const float* W_ih  = (const float*)d_in[1];
    const float* W_hh  = (const float*)d_in[2];
    const float* b_ih  = (const float*)d_in[3];
    const float* b_hh  = (const float*)d_in[4];
    const float* gamma = (const float*)d_in[5];
    const float* beta  = (const float*)d_in[6];
    const float* fc_w  = (const float*)d_in[7];
    const float* fc_b  = (const float*)d_in[8];
    float* out = (float*)d_out;

    static bool attr_set = false;
    if (!attr_set) {
        cudaFuncSetAttribute(proj_mma, cudaFuncAttributeMaxDynamicSharedMemorySize, PSM_TOT);
        cudaFuncSetAttribute(lstm_mma, cudaFuncAttributeMaxDynamicSharedMemorySize, LSM_TOT);
        attr_set = true;
    }

    proj_mma<<<B_ * (T_ / MT), 256, PSM_TOT>>>(x, W_ih);
    lstm_mma<<<LNB, LTHR, LSM_TOT>>>(W_hh, b_ih, b_hh, gamma, beta, fc_w, fc_b, out);
}

// round 16
// speedup vs baseline: 1.2917x; 1.0429x over previous
#include <cuda_runtime.h>
#include <cuda_bf16.h>
#include <cstdint>

#define B_    512
#define T_    2048
#define D_    64
#define H_    66
#define G4    264
#define BG    (B_ * G4)          // x_proj stride per t: [T][B][G4]
#define MT    128                // t-rows per proj block
#define PADW  72                 // proj smem row pad (bf16)
// lstm_mma config
#define LB    4                  // batches per lstm block
#define LNB   (B_ / LB)          // 128 blocks -> one wave
#define LTHR  352                // 11 warps: 3 n8-tiles each
#define KP    88                 // padded K row (bf16) -> 176B stride

// gate-row permutation: smem/xproj column p <- original gate row orig(p)
// p = 4*cell + k, k in {0:i, 1:f, 2:g, 3:o};  orig(p) = k*66 + cell
#define ORIG(p) (((p) & 3) * H_ + ((p) >> 2))

__device__ float    g_xproj[(size_t)T_ * B_ * G4];   // [T][B][G4], permuted cols
__device__ float    g_hT[B_ * H_];
__device__ unsigned g_done = 0;

__device__ __forceinline__ float sigm_(float x) {
    return __fdividef(1.f, 1.f + __expf(-x));
}
__device__ __forceinline__ float tanh_(float x) {
    return 2.f * __fdividef(1.f, 1.f + __expf(-2.f * x)) - 1.f;
}

// ================= mma.sync helpers =================
__device__ __forceinline__ uint32_t smem_u32(const void* p) {
    uint32_t a;
    asm("{ .reg .u64 t; cvta.to.shared.u64 t, %1; cvt.u32.u64 %0, t; }" : "=r"(a) : "l"(p));
    return a;
}
#define LDSM_X4(r, a) \
    asm volatile("ldmatrix.sync.aligned.m8n8.x4.shared.b16 {%0,%1,%2,%3}, [%4];" \
        : "=r"((r)[0]),"=r"((r)[1]),"=r"((r)[2]),"=r"((r)[3]) : "r"(a))
#define LDSM_X2(r, a) \
    asm volatile("ldmatrix.sync.aligned.m8n8.x2.shared.b16 {%0,%1}, [%2];" \
        : "=r"((r)[0]),"=r"((r)[1]) : "r"(a))
#define MMA_BF16(d, a, bb) \
    asm volatile("mma.sync.aligned.m16n8k16.row.col.f32.bf16.bf16.f32 " \
        "{%0,%1,%2,%3}, {%4,%5,%6,%7}, {%8,%9}, {%0,%1,%2,%3};" \
        : "+f"((d)[0]),"+f"((d)[1]),"+f"((d)[2]),"+f"((d)[3]) \
        : "r"((a)[0]),"r"((a)[1]),"r"((a)[2]),"r"((a)[3]), "r"((bb)[0]),"r"((bb)[1]))

__device__ __forceinline__ uint32_t pack_bf16(__nv_bfloat16 lo, __nv_bfloat16 hi) {
    return ((uint32_t)__bfloat16_as_ushort(hi) << 16) | (uint32_t)__bfloat16_as_ushort(lo);
}
__device__ __forceinline__ void split_f4(float4 v, uint2& h, uint2& l) {
    const __nv_bfloat16 h0 = __float2bfloat16(v.x), h1 = __float2bfloat16(v.y),
                        h2 = __float2bfloat16(v.z), h3 = __float2bfloat16(v.w);
    h.x = pack_bf16(h0, h1); h.y = pack_bf16(h2, h3);
    l.x = pack_bf16(__float2bfloat16(v.x - __bfloat162float(h0)),
                    __float2bfloat16(v.y - __bfloat162float(h1)));
    l.y = pack_bf16(__float2bfloat16(v.z - __bfloat162float(h2)),
                    __float2bfloat16(v.w - __bfloat162float(h3)));
}

// ================= projection (R11 validated + gate-row permutation) =================
#define XS_HI 0
#define XS_LO (XS_HI + MT * PADW * 2)
#define WS_HI (XS_LO + MT * PADW * 2)
#define WS_LO (WS_HI + G4 * PADW * 2)
#define PSM_TOT (WS_LO + G4 * PADW * 2)

__global__ __launch_bounds__(256, 1) void proj_mma(const float* __restrict__ x,
                                                   const float* __restrict__ W_ih)
{
    extern __shared__ __align__(16) char smem[];
    const uint32_t sb = smem_u32(smem);
    const int tid  = threadIdx.x;
    const int w    = tid >> 5, lane = tid & 31;
    const int b    = blockIdx.x >> 4;
    const int t0   = (blockIdx.x & 15) * MT;

    {
        const float4* wg = (const float4*)W_ih;
        for (int i = tid; i < G4 * (D_ / 4); i += 256) {
            const int row = i >> 4, c4 = (i & 15) * 4;     // row = permuted col p
            uint2 h, l; split_f4(wg[ORIG(row) * 16 + (i & 15)], h, l);
            const uint32_t off = (uint32_t)(row * PADW + c4) * 2;
            *(uint2*)(smem + WS_HI + off) = h;
            *(uint2*)(smem + WS_LO + off) = l;
        }
    }
    {
        const float4* xg = (const float4*)(x + ((size_t)b * T_ + t0) * D_);
        for (int i = tid; i < MT * (D_ / 4); i += 256) {
            const int row = i >> 4, c4 = (i & 15) * 4;
            uint2 h, l; split_f4(xg[i], h, l);
            const uint32_t off = (uint32_t)(row * PADW + c4) * 2;
            *(uint2*)(smem + XS_HI + off) = h;
            *(uint2*)(smem + XS_LO + off) = l;
        }
    }
    __syncthreads();

    uint32_t aHi[4][4], aLo[4][4];
    {
        const int mat = lane >> 3, r = lane & 7;
        const int row = 16 * w + ((mat & 1) << 3) + r;
        const int colb = (mat >> 1) << 3;
        #pragma unroll
        for (int kc = 0; kc < 4; kc++) {
            const uint32_t o = (uint32_t)(row * PADW + kc * 16 + colb) * 2;
            LDSM_X4(aHi[kc], sb + XS_HI + o);
            LDSM_X4(aLo[kc], sb + XS_LO + o);
        }
    }

    const int L = lane & 15;
    const int nr   = L & 7;
    const int colb = (L >> 3) << 3;
    const int mrow = lane >> 2;
    const int ccol = (lane & 3) * 2;

    for (int nt = 0; nt < 33; nt++) {
        uint32_t bHi[4][2], bLo[4][2];
        const int n = nt * 8 + nr;
        #pragma unroll
        for (int kc = 0; kc < 4; kc++) {
            const uint32_t o = (uint32_t)(n * PADW + kc * 16 + colb) * 2;
            LDSM_X2(bHi[kc], sb + WS_HI + o);
            LDSM_X2(bLo[kc], sb + WS_LO + o);
        }
        float c[4] = {0.f, 0.f, 0.f, 0.f};
        #pragma unroll
        for (int kc = 0; kc < 4; kc++) {
            MMA_BF16(c, aHi[kc], bHi[kc]);
            MMA_BF16(c, aHi[kc], bLo[kc]);
            MMA_BF16(c, aLo[kc], bHi[kc]);
        }
        float* op = g_xproj + (size_t)(t0 + 16 * w + mrow) * BG
                  + (size_t)b * G4 + nt * 8 + ccol;
        *(float2*)op                      = make_float2(c[0], c[1]);
        *(float2*)(op + (size_t)8 * BG)   = make_float2(c[2], c[3]);
    }
}

// ================= recurrence: LB=4, 128 blocks, 1 barrier/step =================
#define ABUF   5632                       // one A buffer: hi 2816 + lo 2816
#define UNI_   (2 * ABUF)                 // 11264
#define W_HI_  (UNI_)
#define W_LO_  (UNI_ + G4 * 176)
#define LSM_TOT (UNI_ + 2 * G4 * 176)     // 104192

__global__ __launch_bounds__(LTHR, 1) void lstm_mma(
    const float* __restrict__ W_hh,  const float* __restrict__ b_ih,
    const float* __restrict__ b_hh,  const float* __restrict__ gamma,
    const float* __restrict__ beta,  const float* __restrict__ fc_w,
    const float* __restrict__ fc_b,  float* __restrict__ out)
{
    extern __shared__ __align__(16) char sm[];
    const uint32_t sb = smem_u32(sm);
    const int tid = threadIdx.x, w = tid >> 5, lane = tid & 31;
    const int b0  = blockIdx.x * LB;
    __shared__ unsigned s_last;
    __shared__ float s_a[H_], s_b[H_];

    // ---- zero both A buffers (rows 4-15 stay zero forever) ----
    for (int i = tid; i < UNI_ / 4; i += LTHR) ((uint32_t*)sm)[i] = 0;

    // ---- split W_hh -> W smem (bf16 hi/lo, permuted rows, k-padded) ----
    for (int i = tid; i < G4 * KP; i += LTHR) {
        const int row = i / KP, col = i % KP;          // row = permuted col p
        const float v = (col < H_) ? W_hh[ORIG(row) * H_ + col] : 0.f;
        const __nv_bfloat16 hi = __float2bfloat16(v);
        const __nv_bfloat16 lo = __float2bfloat16(v - __bfloat162float(hi));
        *(unsigned short*)(sm + W_HI_ + row * 176 + col * 2) = __bfloat16_as_ushort(hi);
        *(unsigned short*)(sm + W_LO_ + row * 176 + col * 2) = __bfloat16_as_ushort(lo);
    }
    __syncthreads();

    // ---- persistent B fragments: 3 n8-tiles per warp ----
    uint32_t bHi[3][5][2], bLo[3][5][2];
    {
        const int L = lane & 15;
        const int nr = L & 7, cb = (L >> 3) << 3;
        #pragma unroll
        for (int nt = 0; nt < 3; nt++) {
            const int n = w * 24 + nt * 8 + nr;
            #pragma unroll
            for (int kc = 0; kc < 5; kc++) {
                const uint32_t o = (uint32_t)(n * 176 + (kc * 16 + cb) * 2);
                LDSM_X2(bHi[nt][kc], sb + W_HI_ + o);
                LDSM_X2(bLo[nt][kc], sb + W_LO_ + o);
            }
        }
    }
    const int ccol = (lane & 3) * 2;
    const int mrow = lane >> 2;
    const int odd  = lane & 1;                  // 0: (i,f) cols; 1: (g,o) cols
    const bool upd = (!odd) && (mrow < LB);     // this lane owns a valid cell update
    const int rb   = (b0 + mrow < B_) ? (b0 + mrow) : (B_ - 1);   // clamped xp batch
    float bias_[3][2];
    int   cell_[3];
    #pragma unroll
    for (int nt = 0; nt < 3; nt++) {
        const int col = w * 24 + nt * 8 + ccol;
        bias_[nt][0] = b_ih[ORIG(col)]     + b_hh[ORIG(col)];
        bias_[nt][1] = b_ih[ORIG(col + 1)] + b_hh[ORIG(col + 1)];
        cell_[nt]    = col >> 2;
    }
    __syncthreads();

    // ---- prologue: xp(0) for row mrow only ----
    float2 pf[3];
    #pragma unroll
    for (int nt = 0; nt < 3; nt++) {
        const int col = w * 24 + nt * 8 + ccol;
        pf[nt] = *(const float2*)(g_xproj + (size_t)rb * G4 + col);
    }

    float c_[3] = {0.f, 0.f, 0.f}, h_[3] = {0.f, 0.f, 0.f};

    for (int t = 0; t < T_; t++) {
        const uint32_t cur = (t & 1) * ABUF, nxt = ((t + 1) & 1) * ABUF;

        // issue xp(t+1) loads early (covered by entire step)
        float2 pfn[3];
        {
            const size_t tb = (size_t)((t + 1 < T_) ? t + 1 : t) * BG;
            #pragma unroll
            for (int nt = 0; nt < 3; nt++) {
                const int col = w * 24 + nt * 8 + ccol;
                pfn[nt] = *(const float2*)(g_xproj + tb + (size_t)rb * G4 + col);
            }
        }

        // A fragments for h(t) from buffer cur
        uint32_t aHi[5][4], aLo[5][4];
        {
            const int mat = lane >> 3, rr = lane & 7;
            const int row = ((mat & 1) << 3) + rr;
            const int cbA = (mat >> 1) << 3;
            #pragma unroll
            for (int kc = 0; kc < 5; kc++) {
                const uint32_t o = (uint32_t)(row * 176 + (kc * 16 + cbA) * 2);
                LDSM_X4(aHi[kc], sb + cur + o);
                LDSM_X4(aLo[kc], sb + cur + 2816 + o);
            }
        }

        // per n-tile: MMA -> activation (row mrow only) -> shfl -> update -> STS h
        #pragma unroll
        for (int nt = 0; nt < 3; nt++) {
            float cA[4] = {0.f,0.f,0.f,0.f}, cB[4] = {0.f,0.f,0.f,0.f}, cC[4] = {0.f,0.f,0.f,0.f};
            #pragma unroll
            for (int kc = 0; kc < 5; kc++) {
                MMA_BF16(cA, aHi[kc], bHi[nt][kc]);
                MMA_BF16(cB, aHi[kc], bLo[nt][kc]);
                MMA_BF16(cC, aLo[kc], bHi[nt][kc]);
            }
            const float p00 = (cA[0]+cB[0]+cC[0]) + pf[nt].x + bias_[nt][0];
            const float p01 = (cA[1]+cB[1]+cC[1]) + pf[nt].y + bias_[nt][1];

            // even lanes hold (i,f) -> sigmoid; odd hold (g,o) -> (tanh, sigmoid)
            const float a0 = odd ? tanh_(p00) : sigm_(p00);
            const float a1 = sigm_(p01);

            // exchange with partner lane (lane^1)
            const float r0 = __shfl_xor_sync(0xffffffffu, a0, 1);
            const float r1 = __shfl_xor_sync(0xffffffffu, a1, 1);

            if (upd) {   // even lane, valid row: i=a0 f=a1 g=r0 o=r1
                c_[nt] = a1 * c_[nt] + a0 * r0;
                h_[nt] = r1 * tanh_(c_[nt]);
                const __nv_bfloat16 hh = __float2bfloat16(h_[nt]);
                const __nv_bfloat16 hl = __float2bfloat16(h_[nt] - __bfloat162float(hh));
                const uint32_t ho = (uint32_t)(mrow * 176 + cell_[nt] * 2);
                *(unsigned short*)(sm + nxt + ho)        = __bfloat16_as_ushort(hh);
                *(unsigned short*)(sm + nxt + 2816 + ho) = __bfloat16_as_ushort(hl);
            }
        }

        #pragma unroll
        for (int j = 0; j < 3; j++) pf[j] = pfn[j];
        __syncthreads();                   // h(t+1) published; fences next LDSM vs STS
    }

    // ---- publish h_T; elect last block ----
    if (upd) {
        #pragma unroll
        for (int nt = 0; nt < 3; nt++)
            g_hT[(b0 + mrow) * H_ + cell_[nt]] = h_[nt];
    }
    __threadfence();
    __syncthreads();
    if (tid == 0) {
        unsigned old = atomicAdd(&g_done, 1);
        s_last = (old == LNB - 1) ? 1u : 0u;
    }
    __syncthreads();
    if (!s_last) return;
    if (tid == 0) g_done = 0;               // reset for graph replay
    __threadfence();

    // ---- BN stats (scratch in dead W region) ----
    float* GTf = (float*)(sm + UNI_);
    if (tid < G4) {
        const int qc = tid / H_, rr = tid % H_;
        float s = 0.f, qs = 0.f;
        for (int b = qc * (B_ / 4); b < (qc + 1) * (B_ / 4); b++) {
            const float v = g_hT[b * H_ + rr];
            s += v; qs += v * v;
        }
        GTf[tid] = s; GTf[G4 + tid] = qs;
    }
    __syncthreads();
    if (tid < H_) {
        const float S = GTf[tid] + GTf[H_ + tid] + GTf[2*H_ + tid] + GTf[3*H_ + tid];
        const float Q = GTf[G4 + tid] + GTf[G4 + H_ + tid] + GTf[G4 + 2*H_ + tid] + GTf[G4 + 3*H_ + tid];
        const float mean = S * (1.f / B_);
        const float var  = Q * (1.f / B_) - mean * mean;
        const float a    = gamma[tid] * rsqrtf(var + 1e-5f);
        s_a[tid] = a * fc_w[tid];
        s_b[tid] = (beta[tid] - mean * a) * fc_w[tid];
    }
    __syncthreads();

    // ---- head ----
    const float f0 = fc_b[0];
    for (int b = tid; b < B_; b += LTHR) {
        float acc = f0;
        #pragma unroll
        for (int jj = 0; jj < H_; jj++)
            acc += s_a[jj] * g_hT[b * H_ + jj] + s_b[jj];
        out[b] = acc;
    }
}

// ================= launch =================
extern "C" void kernel_launch(void* const* d_in, const int* in_sizes, int n_in,
                              void* d_out, int out_size)
{
    const float* x     = (const float*)d_in[0];
    const float* W_ih  = (const float*)d_in[1];
    const float* W_hh  = (const float*)d_in[2];
    const float* b_ih  = (const float*)d_in[3];
    const float* b_hh  = (const float*)d_in[4];
    const float* gamma = (const float*)d_in[5];
    const float* beta  = (const float*)d_in[6];
    const float* fc_w  = (const float*)d_in[7];
    const float* fc_b  = (const float*)d_in[8];
    float* out = (float*)d_out;

    static bool attr_set = false;
    if (!attr_set) {
        cudaFuncSetAttribute(proj_mma, cudaFuncAttributeMaxDynamicSharedMemorySize, PSM_TOT);
        cudaFuncSetAttribute(lstm_mma, cudaFuncAttributeMaxDynamicSharedMemorySize, LSM_TOT);
        attr_set = true;
    }

    proj_mma<<<B_ * (T_ / MT), 256, PSM_TOT>>>(x, W_ih);
    lstm_mma<<<LNB, LTHR, LSM_TOT>>>(W_hh, b_ih, b_hh, gamma, beta, fc_w, fc_b, out);
}

// round 17
// speedup vs baseline: 1.5476x; 1.1981x over previous
#include <cuda_runtime.h>
#include <cuda_bf16.h>
#include <cstdint>

#define B_    512
#define T_    2048
#define D_    64
#define H_    66
#define G4    264
#define BG    (B_ * G4)          // x_proj stride per t: [T][B][G4]
#define MT    128                // t-rows per proj block
#define PADW  72                 // proj smem row pad (bf16)
#define LBPB  2
#define LNBLK (B_ / LBPB)

__device__ float    g_xproj[(size_t)T_ * B_ * G4];   // raw GEMM (no bias)
__device__ float    g_hT[B_ * H_];
__device__ unsigned g_done = 0;

// ================= packed f32x2 helpers (lstm path) =================
#define FMA2(d,a,b,c)   asm("fma.rn.f32x2 %0, %1, %2, %3;" : "=l"(d) : "l"(a), "l"(b), "l"(c))
#define ADD2(d,a,b)     asm("add.rn.f32x2 %0, %1, %2;"     : "=l"(d) : "l"(a), "l"(b))
#define PACK2(d,lo,hi)  asm("mov.b64 %0, {%1, %2};"        : "=l"(d) : "f"(lo), "f"(hi))
#define UNPACK2(lo,hi,s) asm("mov.b64 {%0, %1}, %2;"       : "=f"(lo), "=f"(hi) : "l"(s))

// single-MUFU activations (sm_75+ tanh.approx)
__device__ __forceinline__ float tanhap(float x) {
    float y; asm("tanh.approx.f32 %0, %1;" : "=f"(y) : "f"(x)); return y;
}
__device__ __forceinline__ float sigmap(float x) {
    return fmaf(0.5f, tanhap(0.5f * x), 0.5f);
}

// ================= mma.sync helpers =================
__device__ __forceinline__ uint32_t smem_u32(const void* p) {
    uint32_t a;
    asm("{ .reg .u64 t; cvta.to.shared.u64 t, %1; cvt.u32.u64 %0, t; }" : "=r"(a) : "l"(p));
    return a;
}
#define LDSM_X4(r, a) \
    asm volatile("ldmatrix.sync.aligned.m8n8.x4.shared.b16 {%0,%1,%2,%3}, [%4];" \
        : "=r"((r)[0]),"=r"((r)[1]),"=r"((r)[2]),"=r"((r)[3]) : "r"(a))
#define LDSM_X2(r, a) \
    asm volatile("ldmatrix.sync.aligned.m8n8.x2.shared.b16 {%0,%1}, [%2];" \
        : "=r"((r)[0]),"=r"((r)[1]) : "r"(a))
#define MMA_BF16(d, a, bb) \
    asm volatile("mma.sync.aligned.m16n8k16.row.col.f32.bf16.bf16.f32 " \
        "{%0,%1,%2,%3}, {%4,%5,%6,%7}, {%8,%9}, {%0,%1,%2,%3};" \
        : "+f"((d)[0]),"+f"((d)[1]),"+f"((d)[2]),"+f"((d)[3]) \
        : "r"((a)[0]),"r"((a)[1]),"r"((a)[2]),"r"((a)[3]), "r"((bb)[0]),"r"((bb)[1]))

__device__ __forceinline__ uint32_t pack_bf16(__nv_bfloat16 lo, __nv_bfloat16 hi) {
    return ((uint32_t)__bfloat16_as_ushort(hi) << 16) | (uint32_t)__bfloat16_as_ushort(lo);
}
__device__ __forceinline__ void split_f4(float4 v, uint2& h, uint2& l) {
    const __nv_bfloat16 h0 = __float2bfloat16(v.x), h1 = __float2bfloat16(v.y),
                        h2 = __float2bfloat16(v.z), h3 = __float2bfloat16(v.w);
    h.x = pack_bf16(h0, h1); h.y = pack_bf16(h2, h3);
    l.x = pack_bf16(__float2bfloat16(v.x - __bfloat162float(h0)),
                    __float2bfloat16(v.y - __bfloat162float(h1)));
    l.y = pack_bf16(__float2bfloat16(v.z - __bfloat162float(h2)),
                    __float2bfloat16(v.w - __bfloat162float(h3)));
}

// ================= projection: HMMA bf16-split GEMM (R11, validated) =================
#define XS_HI 0
#define XS_LO (XS_HI + MT * PADW * 2)
#define WS_HI (XS_LO + MT * PADW * 2)
#define WS_LO (WS_HI + G4 * PADW * 2)
#define PSM_TOT (WS_LO + G4 * PADW * 2)

__global__ __launch_bounds__(256, 1) void proj_mma(const float* __restrict__ x,
                                                   const float* __restrict__ W_ih)
{
    extern __shared__ __align__(16) char smem[];
    const uint32_t sb = smem_u32(smem);
    const int tid  = threadIdx.x;
    const int w    = tid >> 5, lane = tid & 31;
    const int b    = blockIdx.x >> 4;
    const int t0   = (blockIdx.x & 15) * MT;

    {
        const float4* wg = (const float4*)W_ih;
        for (int i = tid; i < G4 * (D_ / 4); i += 256) {
            const int row = i >> 4, c4 = (i & 15) * 4;
            uint2 h, l; split_f4(wg[i], h, l);
            const uint32_t off = (uint32_t)(row * PADW + c4) * 2;
            *(uint2*)(smem + WS_HI + off) = h;
            *(uint2*)(smem + WS_LO + off) = l;
        }
    }
    {
        const float4* xg = (const float4*)(x + ((size_t)b * T_ + t0) * D_);
        for (int i = tid; i < MT * (D_ / 4); i += 256) {
            const int row = i >> 4, c4 = (i & 15) * 4;
            uint2 h, l; split_f4(xg[i], h, l);
            const uint32_t off = (uint32_t)(row * PADW + c4) * 2;
            *(uint2*)(smem + XS_HI + off) = h;
            *(uint2*)(smem + XS_LO + off) = l;
        }
    }
    __syncthreads();

    uint32_t aHi[4][4], aLo[4][4];
    {
        const int mat = lane >> 3, r = lane & 7;
        const int row = 16 * w + ((mat & 1) << 3) + r;
        const int colb = (mat >> 1) << 3;
        #pragma unroll
        for (int kc = 0; kc < 4; kc++) {
            const uint32_t o = (uint32_t)(row * PADW + kc * 16 + colb) * 2;
            LDSM_X4(aHi[kc], sb + XS_HI + o);
            LDSM_X4(aLo[kc], sb + XS_LO + o);
        }
    }

    const int L = lane & 15;
    const int nr   = L & 7;
    const int colb = (L >> 3) << 3;
    const int mrow = lane >> 2;
    const int ccol = (lane & 3) * 2;

    for (int nt = 0; nt < 33; nt++) {
        uint32_t bHi[4][2], bLo[4][2];
        const int n = nt * 8 + nr;
        #pragma unroll
        for (int kc = 0; kc < 4; kc++) {
            const uint32_t o = (uint32_t)(n * PADW + kc * 16 + colb) * 2;
            LDSM_X2(bHi[kc], sb + WS_HI + o);
            LDSM_X2(bLo[kc], sb + WS_LO + o);
        }
        float c[4] = {0.f, 0.f, 0.f, 0.f};
        #pragma unroll
        for (int kc = 0; kc < 4; kc++) {
            MMA_BF16(c, aHi[kc], bHi[kc]);
            MMA_BF16(c, aHi[kc], bLo[kc]);
            MMA_BF16(c, aLo[kc], bHi[kc]);
        }
        float* op = g_xproj + (size_t)(t0 + 16 * w + mrow) * BG
                  + (size_t)b * G4 + nt * 8 + ccol;
        *(float2*)op                      = make_float2(c[0], c[1]);
        *(float2*)(op + (size_t)8 * BG)   = make_float2(c[2], c[3]);
    }
}

// ================= recurrence (R11 scalar, tanh.approx activations) =================
__global__ __launch_bounds__(G4, 2) void lstm_kernel(
    const float* __restrict__ W_hh,  const float* __restrict__ b_ih,
    const float* __restrict__ b_hh,  const float* __restrict__ gamma,
    const float* __restrict__ beta,  const float* __restrict__ fc_w,
    const float* __restrict__ fc_b,  float* __restrict__ out)
{
    __shared__ __align__(16) float sh_h[LBPB * 68];
    __shared__ float sh_g[LBPB * G4];
    __shared__ float s_S[G4], s_Q[G4];
    __shared__ float s_a[H_], s_b[H_];
    __shared__ unsigned s_last;

    const int g  = threadIdx.x;
    const int b0 = blockIdx.x * LBPB;

    unsigned long long w[34];
    {
        const float* wr = W_hh + (size_t)g * H_;
        #pragma unroll
        for (int i = 0; i < 33; i++) PACK2(w[i], wr[2*i], wr[2*i + 1]);
        PACK2(w[33], 0.f, 0.f);
    }
    const float biasg = b_ih[g] + b_hh[g];

    for (int i = g; i < LBPB * 68; i += G4) sh_h[i] = 0.f;

    const float* xpp = g_xproj + (size_t)b0 * G4 + g;
    float xpA = xpp[0]  + biasg;
    float xpB = xpp[G4] + biasg;

    float c_ = 0.f, h_ = 0.f;
    const int q0 = (g < LBPB * H_) ? g / H_ : 0;
    const int r  = (g < LBPB * H_) ? g % H_ : 0;
    const bool tg = (g >= 2 * H_) && (g < 3 * H_);
    __syncthreads();

    for (int t = 0; t < T_; t++) {
        const size_t toff = (size_t)((t + 1 < T_) ? t + 1 : t) * BG;
        const float xpA_n = xpp[toff]      + biasg;
        const float xpB_n = xpp[toff + G4] + biasg;

        const ulonglong2* h0 = (const ulonglong2*)(sh_h);
        const ulonglong2* h1 = (const ulonglong2*)(sh_h + 68);
        unsigned long long a0 = 0ull, a1 = 0ull, d0 = 0ull, d1 = 0ull;
        #pragma unroll
        for (int k = 0; k < 17; k++) {
            ulonglong2 v = h0[k];
            ulonglong2 u = h1[k];
            FMA2(a0, w[2*k],     v.x, a0);
            FMA2(a1, w[2*k + 1], v.y, a1);
            FMA2(d0, w[2*k],     u.x, d0);
            FMA2(d1, w[2*k + 1], u.y, d1);
        }
        ADD2(a0, a0, a1); ADD2(d0, d0, d1);
        float lo, hi;
        UNPACK2(lo, hi, a0); const float preA = lo + hi + xpA;
        UNPACK2(lo, hi, d0); const float preB = lo + hi + xpB;

        sh_g[g]      = tg ? tanhap(preA) : sigmap(preA);
        sh_g[G4 + g] = tg ? tanhap(preB) : sigmap(preB);
        __syncthreads();

        if (g < LBPB * H_) {
            const float i_ = sh_g[q0 * G4 + r];
            const float f_ = sh_g[q0 * G4 + H_ + r];
            const float gg = sh_g[q0 * G4 + 2 * H_ + r];
            const float o_ = sh_g[q0 * G4 + 3 * H_ + r];
            c_ = f_ * c_ + i_ * gg;
            h_ = o_ * tanhap(c_);
            sh_h[q0 * 68 + r] = h_;
        }
        __syncthreads();
        xpA = xpA_n; xpB = xpB_n;
    }

    if (g < LBPB * H_)
        g_hT[(b0 + q0) * H_ + r] = h_;
    __threadfence();
    __syncthreads();
    if (g == 0) {
        unsigned old = atomicAdd(&g_done, 1);
        s_last = (old == LNBLK - 1) ? 1u : 0u;
    }
    __syncthreads();
    if (!s_last) return;
    if (g == 0) g_done = 0;
    __threadfence();

    {
        const int qc = g / H_;
        const int rr = g % H_;
        float s = 0.f, qs = 0.f;
        for (int b = qc * (B_ / 4); b < (qc + 1) * (B_ / 4); b++) {
            const float v = g_hT[b * H_ + rr];
            s += v; qs += v * v;
        }
        s_S[g] = s; s_Q[g] = qs;
    }
    __syncthreads();
    if (g < H_) {
        const float S = s_S[g] + s_S[H_ + g] + s_S[2*H_ + g] + s_S[3*H_ + g];
        const float Q = s_Q[g] + s_Q[H_ + g] + s_Q[2*H_ + g] + s_Q[3*H_ + g];
        const float mean = S * (1.f / B_);
        const float var  = Q * (1.f / B_) - mean * mean;
        const float a    = gamma[g] * rsqrtf(var + 1e-5f);
        s_a[g] = a * fc_w[g];
        s_b[g] = (beta[g] - mean * a) * fc_w[g];
    }
    __syncthreads();

    const float f0 = fc_b[0];
    for (int b = g; b < B_; b += G4) {
        float acc = f0;
        #pragma unroll
        for (int jj = 0; jj < H_; jj++)
            acc += s_a[jj] * g_hT[b * H_ + jj] + s_b[jj];
        out[b] = acc;
    }
}

// ================= launch =================
extern "C" void kernel_launch(void* const* d_in, const int* in_sizes, int n_in,
                              void* d_out, int out_size)
{
    const float* x     = (const float*)d_in[0];
    const float* W_ih  = (const float*)d_in[1];
    const float* W_hh  = (const float*)d_in[2];
    const float* b_ih  = (const float*)d_in[3];
    const float* b_hh  = (const float*)d_in[4];
    const float* gamma = (const float*)d_in[5];
    const float* beta  = (const float*)d_in[6];
    const float* fc_w  = (const float*)d_in[7];
    const float* fc_b  = (const float*)d_in[8];
    float* out = (float*)d_out;

    static bool attr_set = false;
    if (!attr_set) {
        cudaFuncSetAttribute(proj_mma, cudaFuncAttributeMaxDynamicSharedMemorySize, PSM_TOT);
        attr_set = true;
    }

    proj_mma<<<B_ * (T_ / MT), 256, PSM_TOT>>>(x, W_ih);
    lstm_kernel<<<LNBLK, G4>>>(W_hh, b_ih, b_hh, gamma, beta, fc_w, fc_b, out);
}